// round 8
// baseline (speedup 1.0000x reference)
#include <cuda_runtime.h>
#include <cuda_bf16.h>
#include <cstdint>

#define BATCH   128
#define NVERT   778
#define NSEG    16
#define SEGSZ   49
#define NPTS    (NSEG * SEGSZ)            // 784
#define GRID_N  32
#define VOLELEM (GRID_N * GRID_N * GRID_N) // 32768
#define NBOX    (2 * BATCH * NSEG)         // 4096
#define SMEM_FLOATS 16384                  // 64 KB dynamic smem -> occ=2

// Gathered segment points, SoA: [hand][b][pt]
__device__ float g_px[2 * BATCH * NPTS];
__device__ float g_py[2 * BATCH * NPTS];
__device__ float g_pz[2 * BATCH * NPTS];
// Boxes: side 0 = boxes from RIGHT hand (hand 0), side 1 = boxes from LEFT hand (hand 1)
__device__ float g_center[NBOX * 3];
__device__ float g_scale[NBOX];

// One CTA per (hand, b): gather seg-indexed vertices into SoA scratch.
__global__ void points_kernel(const float* __restrict__ vertices,
                              const int* __restrict__ seg) {
    int hb   = blockIdx.x;            // hand * BATCH + b
    int b    = hb % BATCH;
    int hand = hb / BATCH;
    const float* vb = vertices + ((size_t)b * 2 + hand) * NVERT * 3;
    int base = hb * NPTS;
    for (int pt = threadIdx.x; pt < NPTS; pt += 256) {
        int n = __ldg(&seg[pt]);
        g_px[base + pt] = __ldg(&vb[n * 3 + 0]);
        g_py[base + pt] = __ldg(&vb[n * 3 + 1]);
        g_pz[base + pt] = __ldg(&vb[n * 3 + 2]);
    }
}

__global__ void boxes_kernel() {
    int t = blockIdx.x * blockDim.x + threadIdx.x;
    if (t >= NBOX) return;
    int k    = t % NSEG;
    int b    = (t / NSEG) % BATCH;
    int side = t / (BATCH * NSEG);
    int hand = side;                  // side0 boxes come from right hand (0), side1 from left (1)
    int base = (hand * BATCH + b) * NPTS + k * SEGSZ;
    float mn0 = 1e30f, mn1 = 1e30f, mn2 = 1e30f;
    float mx0 = -1e30f, mx1 = -1e30f, mx2 = -1e30f;
    for (int j = 0; j < SEGSZ; j++) {
        float v0 = g_px[base + j];
        float v1 = g_py[base + j];
        float v2 = g_pz[base + j];
        mn0 = fminf(mn0, v0); mx0 = fmaxf(mx0, v0);
        mn1 = fminf(mn1, v1); mx1 = fmaxf(mx1, v1);
        mn2 = fminf(mn2, v2); mx2 = fmaxf(mx2, v2);
    }
    float rng = fmaxf(mx0 - mn0, fmaxf(mx1 - mn1, mx2 - mn2));
    g_center[t * 3 + 0] = 0.5f * (mn0 + mx0);
    g_center[t * 3 + 1] = 0.5f * (mn1 + mx1);
    g_center[t * 3 + 2] = 0.5f * (mn2 + mx2);
    g_scale[t] = 0.55f * rng;   // (1 + SCALE_FACTOR) * 0.5 = 1.1 * 0.5
}

__global__ void zero_kernel(float* __restrict__ out) {
    if (threadIdx.x < BATCH) out[threadIdx.x] = 0.0f;
}

__device__ __forceinline__ uint32_t smem_u32(const void* p) {
    return (uint32_t)__cvta_generic_to_shared(p);
}

// One CTA per (side, k, b). Pass A computes 784 grid coords (cached in smem) and
// the touched (z,y,x) bounding box (x rounded to 32B sectors). If the sub-box
// fits 64KB smem, cp.async it in and sample from smem; else sample via L2.
__global__ void __launch_bounds__(256, 2)
sample_kernel(const float* __restrict__ phi_right,
              const float* __restrict__ phi_left,
              float* __restrict__ out) {
    extern __shared__ float vol[];   // SMEM_FLOATS floats = 64 KB

    __shared__ float s_fx[NPTS], s_fy[NPTS], s_fz[NPTS];   // 9408 B static
    __shared__ int s_zlo, s_zhi, s_ylo, s_yhi, s_xlo, s_xhi;
    __shared__ float wsum[8];

    int blk  = blockIdx.x;
    int b    = blk % BATCH;
    int k    = (blk / BATCH) % NSEG;
    int side = blk / (BATCH * NSEG);

    // side 0: out_left  -> points from LEFT hand (1), boxes side 0, volume phi_right
    // side 1: out_right -> points from RIGHT hand (0), boxes side 1, volume phi_left
    const float* phi = (side == 0 ? phi_right : phi_left)
                     + ((size_t)k * BATCH + b) * VOLELEM;
    int phand = 1 - side;
    int pbase = (phand * BATCH + b) * NPTS;

    int boxidx = side * BATCH * NSEG + b * NSEG + k;
    float cx = g_center[boxidx * 3 + 0];
    float cy = g_center[boxidx * 3 + 1];
    float cz = g_center[boxidx * 3 + 2];
    float inv_s = 1.0f / g_scale[boxidx];

    if (threadIdx.x == 0) {
        s_zlo = GRID_N; s_zhi = -1;
        s_ylo = GRID_N; s_yhi = -1;
        s_xlo = GRID_N; s_xhi = -1;
    }
    __syncthreads();

    // ---- Pass A: coords from coalesced SoA scratch; reduce (z,y,x) bbox ----
    {
        int zlo = GRID_N, zhi = -1, ylo = GRID_N, yhi = -1, xlo = GRID_N, xhi = -1;
        for (int pt = threadIdx.x; pt < NPTS; pt += 256) {
            float fx = ((g_px[pbase + pt] - cx) * inv_s + 1.0f) * 0.5f * (GRID_N - 1);
            float fy = ((g_py[pbase + pt] - cy) * inv_s + 1.0f) * 0.5f * (GRID_N - 1);
            float fz = ((g_pz[pbase + pt] - cz) * inv_s + 1.0f) * 0.5f * (GRID_N - 1);
            s_fx[pt] = fx; s_fy[pt] = fy; s_fz[pt] = fz;
            int x0 = (int)floorf(fx), y0 = (int)floorf(fy), z0 = (int)floorf(fz);
            bool rel = (x0 >= -1) && (x0 < GRID_N) &&
                       (y0 >= -1) && (y0 < GRID_N) &&
                       (z0 >= -1) && (z0 < GRID_N);
            if (rel) {
                zlo = min(zlo, max(z0, 0));
                zhi = max(zhi, min(z0 + 1, GRID_N - 1));
                ylo = min(ylo, max(y0, 0));
                yhi = max(yhi, min(y0 + 1, GRID_N - 1));
                xlo = min(xlo, max(x0, 0));
                xhi = max(xhi, min(x0 + 1, GRID_N - 1));
            }
        }
        #pragma unroll
        for (int o = 16; o > 0; o >>= 1) {
            zlo = min(zlo, __shfl_xor_sync(0xFFFFFFFFu, zlo, o));
            zhi = max(zhi, __shfl_xor_sync(0xFFFFFFFFu, zhi, o));
            ylo = min(ylo, __shfl_xor_sync(0xFFFFFFFFu, ylo, o));
            yhi = max(yhi, __shfl_xor_sync(0xFFFFFFFFu, yhi, o));
            xlo = min(xlo, __shfl_xor_sync(0xFFFFFFFFu, xlo, o));
            xhi = max(xhi, __shfl_xor_sync(0xFFFFFFFFu, xhi, o));
        }
        if ((threadIdx.x & 31) == 0) {
            atomicMin(&s_zlo, zlo);
            atomicMax(&s_zhi, zhi);
            atomicMin(&s_ylo, ylo);
            atomicMax(&s_yhi, yhi);
            atomicMin(&s_xlo, xlo);
            atomicMax(&s_xhi, xhi);
        }
    }
    __syncthreads();

    int zlo = s_zlo, zhi = s_zhi, ylo = s_ylo, yhi = s_yhi;
    if (zhi < zlo) return;   // no valid taps -> contributes exactly 0 (block-uniform)

    int yr = yhi - ylo + 1;
    int zr = zhi - zlo + 1;
    int xq = s_xlo & ~7;                  // x start, rounded down to 32B sector
    int xw = ((s_xhi | 7) + 1) - xq;      // x width, multiple of 8 floats
    int nrows = zr * yr;
    bool use_smem = (nrows * xw <= SMEM_FLOATS);   // block-uniform

    if (use_smem) {
        // ---- cp.async sub-box rows (xw floats per row, 16B chunks, aligned) ----
        int cpr = xw >> 2;                 // float4 chunks per row
        int nchunk = nrows * cpr;
        for (int i = threadIdx.x; i < nchunk; i += 256) {
            int row = i / cpr;
            int c   = i - row * cpr;
            int z   = zlo + row / yr;
            int y   = ylo + row - (row / yr) * yr;
            uint32_t dst = smem_u32(vol + (size_t)i * 4);
            const float* gsrc = phi + (z * GRID_N + y) * GRID_N + xq + c * 4;
            asm volatile("cp.async.cg.shared.global [%0], [%1], 16;"
                         :: "r"(dst), "l"(gsrc) : "memory");
        }
        asm volatile("cp.async.commit_group;" ::: "memory");
        asm volatile("cp.async.wait_group 0;" ::: "memory");
        __syncthreads();
    }

    // ---- Pass B: trilinear sampling ----
    float acc = 0.0f;
    for (int pt = threadIdx.x; pt < NPTS; pt += 256) {
        float fx = s_fx[pt], fy = s_fy[pt], fz = s_fz[pt];

        float x0f = floorf(fx), y0f = floorf(fy), z0f = floorf(fz);
        int x0 = (int)x0f, y0 = (int)y0f, z0 = (int)z0f;
        float wx = fx - x0f, wy = fy - y0f, wz = fz - z0f;

        float v = 0.0f;
        #pragma unroll
        for (int dz = 0; dz < 2; dz++) {
            int zz = z0 + dz;
            if ((unsigned)zz >= (unsigned)GRID_N) continue;
            float wwz = dz ? wz : 1.0f - wz;
            #pragma unroll
            for (int dy = 0; dy < 2; dy++) {
                int yy = y0 + dy;
                if ((unsigned)yy >= (unsigned)GRID_N) continue;
                float wwzy = wwz * (dy ? wy : 1.0f - wy);
                const float* row = use_smem
                    ? vol + ((zz - zlo) * yr + (yy - ylo)) * xw - xq
                    : phi + (zz * GRID_N + yy) * GRID_N;
                #pragma unroll
                for (int dx = 0; dx < 2; dx++) {
                    int xx = x0 + dx;
                    if ((unsigned)xx >= (unsigned)GRID_N) continue;
                    v += wwzy * (dx ? wx : 1.0f - wx) *
                         (use_smem ? row[xx] : __ldg(&row[xx]));
                }
            }
        }
        acc += v;
    }

    // Block reduction
    #pragma unroll
    for (int o = 16; o > 0; o >>= 1)
        acc += __shfl_xor_sync(0xFFFFFFFFu, acc, o);

    int lane = threadIdx.x & 31;
    int wid  = threadIdx.x >> 5;
    if (lane == 0) wsum[wid] = acc;
    __syncthreads();
    if (threadIdx.x == 0) {
        float s = 0.0f;
        #pragma unroll
        for (int i = 0; i < 8; i++) s += wsum[i];
        atomicAdd(&out[b], 0.25f * s);
    }
}

extern "C" void kernel_launch(void* const* d_in, const int* in_sizes, int n_in,
                              void* d_out, int out_size) {
    const float* vertices  = (const float*)d_in[0];
    const float* phi_right = (const float*)d_in[1];
    const float* phi_left  = (const float*)d_in[2];
    const int*   seg       = (const int*)d_in[3];
    float* out = (float*)d_out;

    cudaFuncSetAttribute(sample_kernel,
                         cudaFuncAttributeMaxDynamicSharedMemorySize,
                         SMEM_FLOATS * sizeof(float));

    zero_kernel<<<1, 128>>>(out);
    points_kernel<<<2 * BATCH, 256>>>(vertices, seg);
    boxes_kernel<<<(NBOX + 255) / 256, 256>>>();
    sample_kernel<<<2 * NSEG * BATCH, 256, SMEM_FLOATS * sizeof(float)>>>(
        phi_right, phi_left, out);
}

// round 14
// speedup vs baseline: 3.9549x; 3.9549x over previous
#include <cuda_runtime.h>
#include <cuda_bf16.h>
#include <cstdint>

#define BATCH   128
#define NVERT   778
#define NSEG    16
#define SEGSZ   49
#define NPTS    (NSEG * SEGSZ)            // 784
#define GRID_N  32
#define VOLELEM (GRID_N * GRID_N * GRID_N) // 32768
#define NBOX    (2 * BATCH * NSEG)         // 4096

// Gathered segment points, SoA: [hand][b][pt]
__device__ float g_px[2 * BATCH * NPTS];
__device__ float g_py[2 * BATCH * NPTS];
__device__ float g_pz[2 * BATCH * NPTS];
// Boxes: side 0 = boxes from RIGHT hand (hand 0), side 1 = boxes from LEFT hand (hand 1)
__device__ float g_center[NBOX * 3];
__device__ float g_scale[NBOX];

// One CTA per (hand, b): gather seg points into SoA scratch AND compute the 16
// per-segment boxes from smem (fused points+boxes). Block 0 also zeroes out[].
__global__ void __launch_bounds__(256)
prep_kernel(const float* __restrict__ vertices, const int* __restrict__ seg,
            float* __restrict__ out) {
    __shared__ float spx[NPTS], spy[NPTS], spz[NPTS];
    int hb   = blockIdx.x;            // hand * BATCH + b
    int b    = hb % BATCH;
    int hand = hb / BATCH;

    if (hb == 0 && threadIdx.x < BATCH) out[threadIdx.x] = 0.0f;

    const float* vb = vertices + ((size_t)b * 2 + hand) * NVERT * 3;
    int base = hb * NPTS;
    for (int pt = threadIdx.x; pt < NPTS; pt += 256) {
        int n = __ldg(&seg[pt]);
        float x = __ldg(&vb[n * 3 + 0]);
        float y = __ldg(&vb[n * 3 + 1]);
        float z = __ldg(&vb[n * 3 + 2]);
        spx[pt] = x; spy[pt] = y; spz[pt] = z;
        g_px[base + pt] = x;
        g_py[base + pt] = y;
        g_pz[base + pt] = z;
    }
    __syncthreads();

    // Boxes: warp w handles segments w and w+8; lanes split the 49 points.
    int wid = threadIdx.x >> 5, lane = threadIdx.x & 31;
    for (int k = wid; k < NSEG; k += 8) {
        float mn0 = 1e30f, mn1 = 1e30f, mn2 = 1e30f;
        float mx0 = -1e30f, mx1 = -1e30f, mx2 = -1e30f;
        for (int j = lane; j < SEGSZ; j += 32) {
            int idx = k * SEGSZ + j;
            float v0 = spx[idx], v1 = spy[idx], v2 = spz[idx];
            mn0 = fminf(mn0, v0); mx0 = fmaxf(mx0, v0);
            mn1 = fminf(mn1, v1); mx1 = fmaxf(mx1, v1);
            mn2 = fminf(mn2, v2); mx2 = fmaxf(mx2, v2);
        }
        #pragma unroll
        for (int o = 16; o > 0; o >>= 1) {
            mn0 = fminf(mn0, __shfl_xor_sync(0xFFFFFFFFu, mn0, o));
            mx0 = fmaxf(mx0, __shfl_xor_sync(0xFFFFFFFFu, mx0, o));
            mn1 = fminf(mn1, __shfl_xor_sync(0xFFFFFFFFu, mn1, o));
            mx1 = fmaxf(mx1, __shfl_xor_sync(0xFFFFFFFFu, mx1, o));
            mn2 = fminf(mn2, __shfl_xor_sync(0xFFFFFFFFu, mn2, o));
            mx2 = fmaxf(mx2, __shfl_xor_sync(0xFFFFFFFFu, mx2, o));
        }
        if (lane == 0) {
            // side == hand: side0 boxes come from right hand (0), side1 from left (1)
            int boxidx = hand * BATCH * NSEG + b * NSEG + k;
            float rng = fmaxf(mx0 - mn0, fmaxf(mx1 - mn1, mx2 - mn2));
            g_center[boxidx * 3 + 0] = 0.5f * (mn0 + mx0);
            g_center[boxidx * 3 + 1] = 0.5f * (mn1 + mx1);
            g_center[boxidx * 3 + 2] = 0.5f * (mn2 + mx2);
            g_scale[boxidx] = 0.55f * rng;   // (1 + SCALE_FACTOR) * 0.5
        }
    }
}

// One CTA per (side, k, b). Direct trilinear sampling from gmem/L2. Validity
// folded into weights: invalid tap -> weight 0, address clamped in-bounds.
__global__ void __launch_bounds__(256)
sample_kernel(const float* __restrict__ phi_right,
              const float* __restrict__ phi_left,
              float* __restrict__ out) {
    __shared__ float wsum[8];

    int blk  = blockIdx.x;
    int b    = blk % BATCH;
    int k    = (blk / BATCH) % NSEG;
    int side = blk / (BATCH * NSEG);

    // side 0: out_left  -> points from LEFT hand (1), boxes side 0, volume phi_right
    // side 1: out_right -> points from RIGHT hand (0), boxes side 1, volume phi_left
    const float* __restrict__ phi = (side == 0 ? phi_right : phi_left)
                     + ((size_t)k * BATCH + b) * VOLELEM;
    int phand = 1 - side;
    int pbase = (phand * BATCH + b) * NPTS;

    int boxidx = side * BATCH * NSEG + b * NSEG + k;
    float cx = g_center[boxidx * 3 + 0];
    float cy = g_center[boxidx * 3 + 1];
    float cz = g_center[boxidx * 3 + 2];
    float inv_s = 1.0f / g_scale[boxidx];

    float acc = 0.0f;
    #pragma unroll 4
    for (int pt = threadIdx.x; pt < NPTS; pt += 256) {
        float fx = ((g_px[pbase + pt] - cx) * inv_s + 1.0f) * 0.5f * (GRID_N - 1);
        float fy = ((g_py[pbase + pt] - cy) * inv_s + 1.0f) * 0.5f * (GRID_N - 1);
        float fz = ((g_pz[pbase + pt] - cz) * inv_s + 1.0f) * 0.5f * (GRID_N - 1);

        float x0f = floorf(fx), y0f = floorf(fy), z0f = floorf(fz);
        int x0 = (int)x0f, y0 = (int)y0f, z0 = (int)z0f;
        float wx = fx - x0f, wy = fy - y0f, wz = fz - z0f;

        // Fast reject: whole 2x2x2 cell outside -> no loads, no contribution.
        if (x0 < -1 || x0 >= GRID_N || y0 < -1 || y0 >= GRID_N ||
            z0 < -1 || z0 >= GRID_N) continue;

        // 1D weights with validity folded in (invalid tap -> weight 0).
        float wxa = (x0 >= 0)           ? 1.0f - wx : 0.0f;
        float wxb = (x0 + 1 < GRID_N)   ? wx        : 0.0f;
        float wya = (y0 >= 0)           ? 1.0f - wy : 0.0f;
        float wyb = (y0 + 1 < GRID_N)   ? wy        : 0.0f;
        float wza = (z0 >= 0)           ? 1.0f - wz : 0.0f;
        float wzb = (z0 + 1 < GRID_N)   ? wz        : 0.0f;

        // Clamped indices (safe; weight is 0 whenever clamping changes index).
        int xa = max(x0, 0),     xb = min(x0 + 1, GRID_N - 1);
        int ya = max(y0, 0),     yb = min(y0 + 1, GRID_N - 1);
        int za = max(z0, 0),     zb = min(z0 + 1, GRID_N - 1);

        const float* r00 = phi + (za * GRID_N + ya) * GRID_N;
        const float* r01 = phi + (za * GRID_N + yb) * GRID_N;
        const float* r10 = phi + (zb * GRID_N + ya) * GRID_N;
        const float* r11 = phi + (zb * GRID_N + yb) * GRID_N;

        // Front-batched unconditional loads (max MLP, no select in the chain).
        float t000 = __ldg(&r00[xa]);
        float t001 = __ldg(&r00[xb]);
        float t010 = __ldg(&r01[xa]);
        float t011 = __ldg(&r01[xb]);
        float t100 = __ldg(&r10[xa]);
        float t101 = __ldg(&r10[xb]);
        float t110 = __ldg(&r11[xa]);
        float t111 = __ldg(&r11[xb]);

        // Weighted sum (pure FFMA tree).
        float c00 = t000 * wxa + t001 * wxb;
        float c01 = t010 * wxa + t011 * wxb;
        float c10 = t100 * wxa + t101 * wxb;
        float c11 = t110 * wxa + t111 * wxb;
        float c0  = c00 * wya + c01 * wyb;
        float c1  = c10 * wya + c11 * wyb;
        acc += c0 * wza + c1 * wzb;
    }

    // Block reduction
    #pragma unroll
    for (int o = 16; o > 0; o >>= 1)
        acc += __shfl_xor_sync(0xFFFFFFFFu, acc, o);

    int lane = threadIdx.x & 31;
    int wid  = threadIdx.x >> 5;
    if (lane == 0) wsum[wid] = acc;
    __syncthreads();
    if (threadIdx.x == 0) {
        float s = 0.0f;
        #pragma unroll
        for (int i = 0; i < 8; i++) s += wsum[i];
        atomicAdd(&out[b], 0.25f * s);
    }
}

extern "C" void kernel_launch(void* const* d_in, const int* in_sizes, int n_in,
                              void* d_out, int out_size) {
    const float* vertices  = (const float*)d_in[0];
    const float* phi_right = (const float*)d_in[1];
    const float* phi_left  = (const float*)d_in[2];
    const int*   seg       = (const int*)d_in[3];
    float* out = (float*)d_out;

    prep_kernel<<<2 * BATCH, 256>>>(vertices, seg, out);
    sample_kernel<<<2 * NSEG * BATCH, 256>>>(phi_right, phi_left, out);
}

// round 17
// speedup vs baseline: 4.4582x; 1.1273x over previous
#include <cuda_runtime.h>
#include <cuda_bf16.h>
#include <cstdint>

#define BATCH   128
#define NVERT   778
#define NSEG    16
#define SEGSZ   49
#define NPTS    (NSEG * SEGSZ)            // 784
#define GRID_N  32
#define VOLELEM (GRID_N * GRID_N * GRID_N) // 32768
#define NBOX    (2 * BATCH * NSEG)         // 4096

// Gathered segment points, SoA: [hand][b][pt]
__device__ float g_px[2 * BATCH * NPTS];
__device__ float g_py[2 * BATCH * NPTS];
__device__ float g_pz[2 * BATCH * NPTS];
// Boxes: side 0 = boxes from RIGHT hand (hand 0), side 1 = boxes from LEFT hand (hand 1)
__device__ float g_center[NBOX * 3];
__device__ float g_scale[NBOX];

// One CTA per (hand, b): gather seg points into SoA scratch AND compute the 16
// per-segment boxes from smem (fused points+boxes). Block 0 also zeroes out[].
__global__ void __launch_bounds__(256)
prep_kernel(const float* __restrict__ vertices, const int* __restrict__ seg,
            float* __restrict__ out) {
    __shared__ float spx[NPTS], spy[NPTS], spz[NPTS];
    int hb   = blockIdx.x;            // hand * BATCH + b
    int b    = hb % BATCH;
    int hand = hb / BATCH;

    if (hb == 0 && threadIdx.x < BATCH) out[threadIdx.x] = 0.0f;

    const float* vb = vertices + ((size_t)b * 2 + hand) * NVERT * 3;
    int base = hb * NPTS;
    for (int pt = threadIdx.x; pt < NPTS; pt += 256) {
        int n = __ldg(&seg[pt]);
        float x = __ldg(&vb[n * 3 + 0]);
        float y = __ldg(&vb[n * 3 + 1]);
        float z = __ldg(&vb[n * 3 + 2]);
        spx[pt] = x; spy[pt] = y; spz[pt] = z;
        g_px[base + pt] = x;
        g_py[base + pt] = y;
        g_pz[base + pt] = z;
    }
    __syncthreads();

    // Boxes: warp w handles segments w and w+8; lanes split the 49 points.
    int wid = threadIdx.x >> 5, lane = threadIdx.x & 31;
    for (int k = wid; k < NSEG; k += 8) {
        float mn0 = 1e30f, mn1 = 1e30f, mn2 = 1e30f;
        float mx0 = -1e30f, mx1 = -1e30f, mx2 = -1e30f;
        for (int j = lane; j < SEGSZ; j += 32) {
            int idx = k * SEGSZ + j;
            float v0 = spx[idx], v1 = spy[idx], v2 = spz[idx];
            mn0 = fminf(mn0, v0); mx0 = fmaxf(mx0, v0);
            mn1 = fminf(mn1, v1); mx1 = fmaxf(mx1, v1);
            mn2 = fminf(mn2, v2); mx2 = fmaxf(mx2, v2);
        }
        #pragma unroll
        for (int o = 16; o > 0; o >>= 1) {
            mn0 = fminf(mn0, __shfl_xor_sync(0xFFFFFFFFu, mn0, o));
            mx0 = fmaxf(mx0, __shfl_xor_sync(0xFFFFFFFFu, mx0, o));
            mn1 = fminf(mn1, __shfl_xor_sync(0xFFFFFFFFu, mn1, o));
            mx1 = fmaxf(mx1, __shfl_xor_sync(0xFFFFFFFFu, mx1, o));
            mn2 = fminf(mn2, __shfl_xor_sync(0xFFFFFFFFu, mn2, o));
            mx2 = fmaxf(mx2, __shfl_xor_sync(0xFFFFFFFFu, mx2, o));
        }
        if (lane == 0) {
            // side == hand: side0 boxes come from right hand (0), side1 from left (1)
            int boxidx = hand * BATCH * NSEG + b * NSEG + k;
            float rng = fmaxf(mx0 - mn0, fmaxf(mx1 - mn1, mx2 - mn2));
            g_center[boxidx * 3 + 0] = 0.5f * (mn0 + mx0);
            g_center[boxidx * 3 + 1] = 0.5f * (mn1 + mx1);
            g_center[boxidx * 3 + 2] = 0.5f * (mn2 + mx2);
            g_scale[boxidx] = 0.55f * rng;   // (1 + SCALE_FACTOR) * 0.5
        }
    }
}

// One CTA per (side, k, b). Direct trilinear sampling from gmem/L2.
// Fully branchless: per-tap validity predicates the load (no memory traffic
// for invalid taps) and zeroes the weight; no control flow in the loop, so
// ptxas can front-batch all loads across the unrolled iterations.
__global__ void __launch_bounds__(256)
sample_kernel(const float* __restrict__ phi_right,
              const float* __restrict__ phi_left,
              float* __restrict__ out) {
    __shared__ float wsum[8];

    int blk  = blockIdx.x;
    int b    = blk % BATCH;
    int k    = (blk / BATCH) % NSEG;
    int side = blk / (BATCH * NSEG);

    // side 0: out_left  -> points from LEFT hand (1), boxes side 0, volume phi_right
    // side 1: out_right -> points from RIGHT hand (0), boxes side 1, volume phi_left
    const float* __restrict__ phi = (side == 0 ? phi_right : phi_left)
                     + ((size_t)k * BATCH + b) * VOLELEM;
    int phand = 1 - side;
    int pbase = (phand * BATCH + b) * NPTS;

    int boxidx = side * BATCH * NSEG + b * NSEG + k;
    float cx = g_center[boxidx * 3 + 0];
    float cy = g_center[boxidx * 3 + 1];
    float cz = g_center[boxidx * 3 + 2];
    float inv_s = 1.0f / g_scale[boxidx];

    float acc = 0.0f;
    #pragma unroll 4
    for (int pt = threadIdx.x; pt < NPTS; pt += 256) {
        float fx = ((g_px[pbase + pt] - cx) * inv_s + 1.0f) * 0.5f * (GRID_N - 1);
        float fy = ((g_py[pbase + pt] - cy) * inv_s + 1.0f) * 0.5f * (GRID_N - 1);
        float fz = ((g_pz[pbase + pt] - cz) * inv_s + 1.0f) * 0.5f * (GRID_N - 1);

        float x0f = floorf(fx), y0f = floorf(fy), z0f = floorf(fz);
        int x0 = (int)x0f, y0 = (int)y0f, z0 = (int)z0f;
        float wx = fx - x0f, wy = fy - y0f, wz = fz - z0f;

        // Exact per-tap validity (no pre-bounding; works for any x0).
        bool vxa = (x0 >= 0)  && (x0 < GRID_N);
        bool vxb = (x0 >= -1) && (x0 < GRID_N - 1);
        bool vya = (y0 >= 0)  && (y0 < GRID_N);
        bool vyb = (y0 >= -1) && (y0 < GRID_N - 1);
        bool vza = (z0 >= 0)  && (z0 < GRID_N);
        bool vzb = (z0 >= -1) && (z0 < GRID_N - 1);

        // Weights with validity folded in.
        float wxa = vxa ? 1.0f - wx : 0.0f;
        float wxb = vxb ? wx        : 0.0f;
        float wya = vya ? 1.0f - wy : 0.0f;
        float wyb = vyb ? wy        : 0.0f;
        float wza = vza ? 1.0f - wz : 0.0f;
        float wzb = vzb ? wz        : 0.0f;

        // Clamped indices (weight is 0 whenever clamping changes the index).
        int xa = min(max(x0, 0), GRID_N - 1), xb = min(max(x0 + 1, 0), GRID_N - 1);
        int ya = min(max(y0, 0), GRID_N - 1), yb = min(max(y0 + 1, 0), GRID_N - 1);
        int za = min(max(z0, 0), GRID_N - 1), zb = min(max(z0 + 1, 0), GRID_N - 1);

        const float* r00 = phi + (za * GRID_N + ya) * GRID_N;
        const float* r01 = phi + (za * GRID_N + yb) * GRID_N;
        const float* r10 = phi + (zb * GRID_N + ya) * GRID_N;
        const float* r11 = phi + (zb * GRID_N + yb) * GRID_N;

        // Predicated loads: invalid taps issue no memory transaction.
        float t000 = (vza && vya && vxa) ? __ldg(&r00[xa]) : 0.0f;
        float t001 = (vza && vya && vxb) ? __ldg(&r00[xb]) : 0.0f;
        float t010 = (vza && vyb && vxa) ? __ldg(&r01[xa]) : 0.0f;
        float t011 = (vza && vyb && vxb) ? __ldg(&r01[xb]) : 0.0f;
        float t100 = (vzb && vya && vxa) ? __ldg(&r10[xa]) : 0.0f;
        float t101 = (vzb && vya && vxb) ? __ldg(&r10[xb]) : 0.0f;
        float t110 = (vzb && vyb && vxa) ? __ldg(&r11[xa]) : 0.0f;
        float t111 = (vzb && vyb && vxb) ? __ldg(&r11[xb]) : 0.0f;

        // Weighted sum (pure FFMA tree).
        float c00 = t000 * wxa + t001 * wxb;
        float c01 = t010 * wxa + t011 * wxb;
        float c10 = t100 * wxa + t101 * wxb;
        float c11 = t110 * wxa + t111 * wxb;
        float c0  = c00 * wya + c01 * wyb;
        float c1  = c10 * wya + c11 * wyb;
        acc += c0 * wza + c1 * wzb;
    }

    // Block reduction
    #pragma unroll
    for (int o = 16; o > 0; o >>= 1)
        acc += __shfl_xor_sync(0xFFFFFFFFu, acc, o);

    int lane = threadIdx.x & 31;
    int wid  = threadIdx.x >> 5;
    if (lane == 0) wsum[wid] = acc;
    __syncthreads();
    if (threadIdx.x == 0) {
        float s = 0.0f;
        #pragma unroll
        for (int i = 0; i < 8; i++) s += wsum[i];
        atomicAdd(&out[b], 0.25f * s);
    }
}

extern "C" void kernel_launch(void* const* d_in, const int* in_sizes, int n_in,
                              void* d_out, int out_size) {
    const float* vertices  = (const float*)d_in[0];
    const float* phi_right = (const float*)d_in[1];
    const float* phi_left  = (const float*)d_in[2];
    const int*   seg       = (const int*)d_in[3];
    float* out = (float*)d_out;

    prep_kernel<<<2 * BATCH, 256>>>(vertices, seg, out);
    sample_kernel<<<2 * NSEG * BATCH, 256>>>(phi_right, phi_left, out);
}